// round 1
// baseline (speedup 1.0000x reference)
#include <cuda_runtime.h>

// Double-precision global accumulator (scratch; no allocation allowed).
__device__ double g_accum;

__global__ void yolo_zero_kernel() {
    g_accum = 0.0;
}

__global__ __launch_bounds__(256) void yolo_loss_kernel(
    const float* __restrict__ pred,   // [B, 7*7*30]
    const float* __restrict__ targ,   // [B, 7*7*25]
    long n_cells)                     // B * 49
{
    long g = (long)blockIdx.x * blockDim.x + threadIdx.x;

    float loss = 0.0f;
    if (g < n_cells) {
        const float* __restrict__ P = pred + g * 30;
        const float* __restrict__ T = targ + g * 25;

        float c1 = __ldg(P + 4);
        float c2 = __ldg(P + 9);
        float c  = __ldg(T + 4);

        bool present = (c == 1.0f);
        bool r1 = (c1 > c2);

        if (present) {
            // objectness: responsible predictor vs target confidence
            float dobj = (r1 ? c1 : c2) - c;
            loss = dobj * dobj;

            // class loss: sum_{i=0..19} (P[10+i] - T[5+i])^2
            float cls = 0.0f;
            #pragma unroll
            for (int i = 0; i < 20; ++i) {
                float d = __ldg(P + 10 + i) - __ldg(T + 5 + i);
                cls = fmaf(d, d, cls);
            }

            // box loss: centers + sqrt(h/w), responsible predictor
            int o = r1 ? 0 : 5;
            float box = 0.0f;
            #pragma unroll
            for (int i = 0; i < 2; ++i) {
                float d = __ldg(P + o + i) - __ldg(T + i);
                box = fmaf(d, d, box);
            }
            #pragma unroll
            for (int i = 0; i < 2; ++i) {
                float d = sqrtf(__ldg(P + o + 2 + i)) - sqrtf(__ldg(T + 2 + i));
                box = fmaf(d, d, box);
            }

            loss += cls + 5.0f * box;
        } else {
            // no object: 0.5 * (c1^2 + c2^2); class/box contribute 0 — skip loads
            loss = 0.5f * fmaf(c1, c1, c2 * c2);
        }
    }

    // warp reduction
    #pragma unroll
    for (int off = 16; off > 0; off >>= 1)
        loss += __shfl_xor_sync(0xFFFFFFFFu, loss, off);

    // block reduction via shared memory
    __shared__ float warp_sums[8];  // 256 threads = 8 warps
    int wid = threadIdx.x >> 5;
    int lid = threadIdx.x & 31;
    if (lid == 0) warp_sums[wid] = loss;
    __syncthreads();

    if (wid == 0) {
        float b = (lid < 8) ? warp_sums[lid] : 0.0f;
        #pragma unroll
        for (int off = 4; off > 0; off >>= 1)
            b += __shfl_xor_sync(0xFFFFFFFFu, b, off);
        if (lid == 0)
            atomicAdd(&g_accum, (double)b);
    }
}

__global__ void yolo_finish_kernel(float* __restrict__ out) {
    out[0] = (float)g_accum;
}

extern "C" void kernel_launch(void* const* d_in, const int* in_sizes, int n_in,
                              void* d_out, int out_size) {
    const float* pred = (const float*)d_in[0];   // predictions [B, 1470]
    const float* targ = (const float*)d_in[1];   // targets     [B, 1225]
    float* out = (float*)d_out;

    long B = (long)in_sizes[0] / 1470;
    long n_cells = B * 49;

    int threads = 256;
    long blocks = (n_cells + threads - 1) / threads;

    yolo_zero_kernel<<<1, 1>>>();
    yolo_loss_kernel<<<(unsigned)blocks, threads>>>(pred, targ, n_cells);
    yolo_finish_kernel<<<1, 1>>>(out);
}